// round 1
// baseline (speedup 1.0000x reference)
#include <cuda_runtime.h>
#include <math.h>
#include <float.h>

// Problem constants
#define BB 4
#define NN 256
#define DD 256
#define HH 4
#define DH 64
#define INNER 256
#define LL 2
#define FFH 1024
#define FFHALF 512

// ---------------- device scratch (no runtime allocation allowed) ----------------
__device__ float g_x   [BB*NN*DD];
__device__ float g_xn  [BB*NN*DD];
__device__ float g_q   [BB*NN*INNER];
__device__ float g_k   [BB*NN*INNER];
__device__ float g_v   [BB*NN*INNER];
__device__ float g_eb  [BB*NN*NN*HH];
__device__ float g_attn[BB*HH*NN*NN];
__device__ float g_Ag  [BB*HH*NN*INNER];
__device__ float g_outv[BB*HH*NN*DH];
__device__ float g_tmp [BB*NN*INNER];
__device__ float g_hg  [BB*NN*FFH];
__device__ float g_t   [BB*NN*FFHALF];
__device__ unsigned char g_adj[BB*NN*NN];
__device__ int   g_valid[BB*NN];
__device__ float g_ls[BB];

__device__ __forceinline__ float gelu_f(float x) {
    return 0.5f * x * (1.0f + erff(x * 0.70710678118654752440f));
}

__device__ __forceinline__ int hop_of(int n) {
    return (n == 0) ? 0 : ((n < 128) ? 1 : 2);
}

__device__ __forceinline__ void edge_features(int i, int j, float cix, float ciy,
                                              float cjx, float cjy, float invls,
                                              float* f) {
    float dx = cjx - cix, dy = cjy - ciy;
    float dist = sqrtf(dx * dx + dy * dy + 1e-8f);
    f[0] = dx; f[1] = dy; f[2] = dist; f[3] = dist * invls;
    float qic = (i == 0) ? 1.f : 0.f;
    float kic = (j == 0) ? 1.f : 0.f;
    float ey  = (i == j) ? 1.f : 0.f;
    f[4] = qic; f[5] = kic; f[6] = ey;
    f[7] = ((i != 0) && (j != 0) && (i != j)) ? 1.f : 0.f;
    int hi = hop_of(i), hj = hop_of(j);
    f[8] = (hi == hj) ? 1.f : 0.f;
    f[9] = fabsf((float)(hj - hi));
    f[10] = 0.f;
}

// ---------------- copy in/out ----------------
__global__ void k_copy_in(const float* __restrict__ src) {
    int i = blockIdx.x * blockDim.x + threadIdx.x;
    g_x[i] = src[i];
}
__global__ void k_copy_out(float* __restrict__ dst) {
    int i = blockIdx.x * blockDim.x + threadIdx.x;
    dst[i] = g_x[i];
}

// ---------------- graph build ----------------
__global__ void k_valid_ls(const float* __restrict__ x, const float* __restrict__ coords) {
    int b = blockIdx.x, n = threadIdx.x;
    const float* xr = x + (size_t)(b * NN + n) * DD;
    float s = 0.f;
    for (int d = 0; d < DD; d++) s += fabsf(xr[d]);
    int val = (s > 0.f) || (n == 0);
    g_valid[b * NN + n] = val;
    float cx = coords[(b * NN + n) * 2 + 0];
    float cy = coords[(b * NN + n) * 2 + 1];
    float cd = sqrtf(cx * cx + cy * cy + 1e-8f);
    int nvm = val && (n > 0);
    __shared__ float sd[NN];
    __shared__ float sc[NN];
    sd[n] = nvm ? cd : 0.f;
    sc[n] = nvm ? 1.f : 0.f;
    __syncthreads();
    for (int st = 128; st > 0; st >>= 1) {
        if (n < st) { sd[n] += sd[n + st]; sc[n] += sc[n + st]; }
        __syncthreads();
    }
    if (n == 0) {
        float cnt = fmaxf(sc[0], 1.f);
        float ls = sd[0] / cnt;
        g_ls[b] = (ls > 0.f) ? ls : 1.f;
    }
}

__global__ void k_adj(const float* __restrict__ coords) {
    int b = blockIdx.x, i = threadIdx.x;
    int vi = g_valid[b * NN + i];
    unsigned char* row = g_adj + (size_t)(b * NN + i) * NN;
    for (int j = 0; j < NN; j++) {
        int vj = g_valid[b * NN + j];
        int a = (i == j);
        if (i == 0 && j > 0) a |= vj;
        if (j == 0 && i > 0) a |= vi;
        row[j] = (unsigned char)a;
    }
    __syncthreads();
    // KNN (k=3) among nodes 1..255, valid only, self excluded; symmetrize
    if (i >= 1 && vi) {
        float cix = coords[(b * NN + i) * 2 + 0];
        float ciy = coords[(b * NN + i) * 2 + 1];
        float bd0 = FLT_MAX, bd1 = FLT_MAX, bd2 = FLT_MAX;
        int   bi0 = -1, bi1 = -1, bi2 = -1;
        for (int j = 1; j < NN; j++) {
            if (j == i) continue;
            if (!g_valid[b * NN + j]) continue;
            float dx = coords[(b * NN + j) * 2 + 0] - cix;
            float dy = coords[(b * NN + j) * 2 + 1] - ciy;
            float d2 = dx * dx + dy * dy;
            if (d2 < bd0)      { bd2 = bd1; bi2 = bi1; bd1 = bd0; bi1 = bi0; bd0 = d2; bi0 = j; }
            else if (d2 < bd1) { bd2 = bd1; bi2 = bi1; bd1 = d2; bi1 = j; }
            else if (d2 < bd2) { bd2 = d2; bi2 = j; }
        }
        if (bi0 >= 0) { g_adj[(b * NN + i) * NN + bi0] = 1; g_adj[(b * NN + bi0) * NN + i] = 1; }
        if (bi1 >= 0) { g_adj[(b * NN + i) * NN + bi1] = 1; g_adj[(b * NN + bi1) * NN + i] = 1; }
        if (bi2 >= 0) { g_adj[(b * NN + i) * NN + bi2] = 1; g_adj[(b * NN + bi2) * NN + i] = 1; }
    }
}

// ---------------- layernorm (one block per row, 256 threads) ----------------
__global__ void k_layernorm(const float* __restrict__ x, const float* __restrict__ w,
                            const float* __restrict__ bia, float* __restrict__ out) {
    int row = blockIdx.x, t = threadIdx.x;
    float v = x[(size_t)row * DD + t];
    __shared__ float red[DD];
    red[t] = v;
    __syncthreads();
    for (int s = 128; s > 0; s >>= 1) {
        if (t < s) red[t] += red[t + s];
        __syncthreads();
    }
    float mean = red[0] * (1.f / DD);
    __syncthreads();
    float d = v - mean;
    red[t] = d * d;
    __syncthreads();
    for (int s = 128; s > 0; s >>= 1) {
        if (t < s) red[t] += red[t + s];
        __syncthreads();
    }
    float var = red[0] * (1.f / DD);
    out[(size_t)row * DD + t] = d * rsqrtf(var + 1e-5f) * w[t] + bia[t];
}

// ---------------- generic tiled GEMM: C = A[M,K]@W[K,Nc] + bias (+ residual) ----------------
// Requires M%64==0, Nc%64==0, K%16==0. 256 threads, each computes 4x4.
__global__ void k_gemm(const float* __restrict__ A, const float* __restrict__ W,
                       const float* __restrict__ bias, const float* __restrict__ resid,
                       float* __restrict__ C, int M, int Nc, int K) {
    __shared__ float As[64][16];
    __shared__ float Ws[16][64];
    int bm = blockIdx.y, bn = blockIdx.x;
    int tid = threadIdx.x;
    int ty = tid >> 4, tx = tid & 15;
    float acc[4][4] = {};
    for (int kt = 0; kt < K; kt += 16) {
        int e0 = tid * 4;
#pragma unroll
        for (int u = 0; u < 4; u++) {
            int e = e0 + u;
            int m = e >> 4, kk = e & 15;
            As[m][kk] = A[(size_t)(bm * 64 + m) * K + kt + kk];
        }
#pragma unroll
        for (int u = 0; u < 4; u++) {
            int e = e0 + u;
            int kk = e >> 6, n = e & 63;
            Ws[kk][n] = W[(size_t)(kt + kk) * Nc + bn * 64 + n];
        }
        __syncthreads();
#pragma unroll
        for (int kk = 0; kk < 16; kk++) {
            float a[4], w[4];
#pragma unroll
            for (int r = 0; r < 4; r++) a[r] = As[ty * 4 + r][kk];
#pragma unroll
            for (int c = 0; c < 4; c++) w[c] = Ws[kk][tx * 4 + c];
#pragma unroll
            for (int r = 0; r < 4; r++)
#pragma unroll
                for (int c = 0; c < 4; c++) acc[r][c] += a[r] * w[c];
        }
        __syncthreads();
    }
#pragma unroll
    for (int r = 0; r < 4; r++) {
#pragma unroll
        for (int c = 0; c < 4; c++) {
            int row = bm * 64 + ty * 4 + r;
            int col = bn * 64 + tx * 4 + c;
            float v = acc[r][c];
            if (bias) v += bias[col];
            if (resid) v += resid[(size_t)row * Nc + col];
            C[(size_t)row * Nc + col] = v;
        }
    }
}

// ---------------- eb: per adjacent edge, gelu(e@W1+b1)@W2+b2 -> 4 heads ----------------
__global__ void k_eb(const float* __restrict__ coords,
                     const float* __restrict__ w1, const float* __restrict__ b1,
                     const float* __restrict__ w2, const float* __restrict__ b2) {
    int gw = (blockIdx.x * blockDim.x + threadIdx.x) >> 5;
    int lane = threadIdx.x & 31;
    if (gw >= BB * NN * NN) return;
    if (!g_adj[gw]) return;
    int b = gw >> 16, i = (gw >> 8) & 255, j = gw & 255;
    float invls = 1.f / fmaxf(g_ls[b], 1e-6f);
    float f[11];
    edge_features(i, j,
                  coords[(b * NN + i) * 2 + 0], coords[(b * NN + i) * 2 + 1],
                  coords[(b * NN + j) * 2 + 0], coords[(b * NN + j) * 2 + 1],
                  invls, f);
    float a0 = 0, a1 = 0, a2 = 0, a3 = 0;
#pragma unroll
    for (int t = 0; t < 8; t++) {
        int m = t * 32 + lane;
        float h = b1[m];
#pragma unroll
        for (int q = 0; q < 11; q++) h += f[q] * w1[q * INNER + m];
        h = gelu_f(h);
        a0 += h * w2[m * 4 + 0];
        a1 += h * w2[m * 4 + 1];
        a2 += h * w2[m * 4 + 2];
        a3 += h * w2[m * 4 + 3];
    }
#pragma unroll
    for (int off = 16; off; off >>= 1) {
        a0 += __shfl_xor_sync(0xffffffffu, a0, off);
        a1 += __shfl_xor_sync(0xffffffffu, a1, off);
        a2 += __shfl_xor_sync(0xffffffffu, a2, off);
        a3 += __shfl_xor_sync(0xffffffffu, a3, off);
    }
    if (lane == 0) {
        float* o = g_eb + (size_t)gw * 4;
        o[0] = a0 + b2[0];
        o[1] = a1 + b2[1];
        o[2] = a2 + b2[2];
        o[3] = a3 + b2[3];
    }
}

// ---------------- attention scores + softmax ----------------
__global__ void k_attn() {
    int blk = blockIdx.x;                 // b*1024 + h*256 + i
    int j = threadIdx.x;
    int i = blk & 255, h = (blk >> 8) & 3, b = blk >> 10;
    __shared__ float qs[DH];
    if (j < DH) qs[j] = g_q[(size_t)(b * NN + i) * INNER + h * DH + j];
    __syncthreads();
    int adj = g_adj[(b * NN + i) * NN + j];
    float sim = -FLT_MAX;
    if (adj) {
        const float* kr = g_k + (size_t)(b * NN + j) * INNER + h * DH;
        float d = 0.f;
#pragma unroll
        for (int t = 0; t < DH; t++) d += qs[t] * kr[t];
        sim = d * 0.125f + g_eb[((size_t)(b * NN + i) * NN + j) * 4 + h];
    }
    __shared__ float red[NN];
    red[j] = sim;
    __syncthreads();
    for (int s = 128; s > 0; s >>= 1) {
        if (j < s) red[j] = fmaxf(red[j], red[j + s]);
        __syncthreads();
    }
    float mx = red[0];
    __syncthreads();
    float ex = adj ? expf(sim - mx) : 0.f;
    red[j] = ex;
    __syncthreads();
    for (int s = 128; s > 0; s >>= 1) {
        if (j < s) red[j] += red[j + s];
        __syncthreads();
    }
    g_attn[((size_t)(b * HH + h) * NN + i) * NN + j] = ex / red[0];
}

// ---------------- out_v = attn @ v ----------------
__global__ void k_outv() {
    int blk = blockIdx.x;                 // b*1024 + h*256 + i
    int d = threadIdx.x;                  // 64
    int i = blk & 255, h = (blk >> 8) & 3, b = blk >> 10;
    __shared__ float sa[NN];
    for (int t = d; t < NN; t += 64)
        sa[t] = g_attn[((size_t)(b * HH + h) * NN + i) * NN + t];
    __syncthreads();
    float acc = 0.f;
    for (int j = 0; j < NN; j++) {
        float a = sa[j];
        if (a != 0.f) acc += a * g_v[(size_t)(b * NN + j) * INNER + h * DH + d];
    }
    g_outv[((size_t)(b * HH + h) * NN + i) * DH + d] = acc;
}

// ---------------- A_g = sum_j attn * gelu(e@ev_w1+b1), sparse over adj ----------------
__global__ void k_Ag(const float* __restrict__ coords,
                     const float* __restrict__ w1, const float* __restrict__ b1) {
    int b = blockIdx.x >> 8, i = blockIdx.x & 255, m = threadIdx.x;
    __shared__ float sa[HH][NN];
    __shared__ float scx[NN], scy[NN];
    __shared__ unsigned char sadj[NN];
#pragma unroll
    for (int h = 0; h < HH; h++)
        sa[h][m] = g_attn[((size_t)(b * HH + h) * NN + i) * NN + m];
    sadj[m] = g_adj[(b * NN + i) * NN + m];
    scx[m] = coords[(b * NN + m) * 2 + 0];
    scy[m] = coords[(b * NN + m) * 2 + 1];
    __syncthreads();
    float w1r[11];
#pragma unroll
    for (int f = 0; f < 11; f++) w1r[f] = w1[f * INNER + m];
    float b1m = b1[m];
    float invls = 1.f / fmaxf(g_ls[b], 1e-6f);
    float cix = scx[i], ciy = scy[i];
    int hi = hop_of(i);
    float qic = (i == 0) ? 1.f : 0.f;
    float acc0 = 0, acc1 = 0, acc2 = 0, acc3 = 0;
    for (int j = 0; j < NN; j++) {
        if (!sadj[j]) continue;
        float dx = scx[j] - cix, dy = scy[j] - ciy;
        float dist = sqrtf(dx * dx + dy * dy + 1e-8f);
        float kic = (j == 0) ? 1.f : 0.f;
        float ey = (i == j) ? 1.f : 0.f;
        float isnn = ((i != 0) && (j != 0) && (i != j)) ? 1.f : 0.f;
        int hj = hop_of(j);
        float hv = b1m + dx * w1r[0] + dy * w1r[1] + dist * w1r[2]
                 + (dist * invls) * w1r[3] + qic * w1r[4] + kic * w1r[5]
                 + ey * w1r[6] + isnn * w1r[7]
                 + ((hi == hj) ? 1.f : 0.f) * w1r[8]
                 + fabsf((float)(hj - hi)) * w1r[9];
        hv = gelu_f(hv);
        acc0 += sa[0][j] * hv;
        acc1 += sa[1][j] * hv;
        acc2 += sa[2][j] * hv;
        acc3 += sa[3][j] * hv;
    }
    g_Ag[((size_t)(b * HH + 0) * NN + i) * INNER + m] = acc0;
    g_Ag[((size_t)(b * HH + 1) * NN + i) * INNER + m] = acc1;
    g_Ag[((size_t)(b * HH + 2) * NN + i) * INNER + m] = acc2;
    g_Ag[((size_t)(b * HH + 3) * NN + i) * INNER + m] = acc3;
}

// ---------------- tmp = out_v + A_g @ ev_w2 + ev_b2 ----------------
__global__ void k_combine(const float* __restrict__ w2, const float* __restrict__ b2) {
    int b = blockIdx.x >> 8, i = blockIdx.x & 255, c = threadIdx.x;
    __shared__ float sg[HH][INNER];
#pragma unroll
    for (int h = 0; h < HH; h++)
        sg[h][c] = g_Ag[((size_t)(b * HH + h) * NN + i) * INNER + c];
    __syncthreads();
    int h = c >> 6;
    float acc = b2[c];
    for (int m = 0; m < INNER; m++) acc += sg[h][m] * w2[(size_t)m * INNER + c];
    acc += g_outv[((size_t)(b * HH + h) * NN + i) * DH + (c & 63)];
    g_tmp[(size_t)(b * NN + i) * INNER + c] = acc;
}

// ---------------- GLU elementwise: t = a * gelu(g) ----------------
__global__ void k_glu() {
    int idx = blockIdx.x * blockDim.x + threadIdx.x;   // < 1024*512
    int r = idx >> 9, c = idx & 511;
    float a = g_hg[(size_t)r * FFH + c];
    float g = g_hg[(size_t)r * FFH + FFHALF + c];
    g_t[idx] = a * gelu_f(g);
}

// ---------------- host launch ----------------
extern "C" void kernel_launch(void* const* d_in, const int* in_sizes, int n_in,
                              void* d_out, int out_size) {
    const float* x      = (const float*)d_in[0];
    const float* coords = (const float*)d_in[1];
    const float* Wq     = (const float*)d_in[2];
    const float* Wk     = (const float*)d_in[3];
    const float* Wv     = (const float*)d_in[4];
    const float* ebw1   = (const float*)d_in[5];
    const float* ebb1   = (const float*)d_in[6];
    const float* ebw2   = (const float*)d_in[7];
    const float* ebb2   = (const float*)d_in[8];
    const float* evw1   = (const float*)d_in[9];
    const float* evb1   = (const float*)d_in[10];
    const float* evw2   = (const float*)d_in[11];
    const float* evb2   = (const float*)d_in[12];
    const float* Wo     = (const float*)d_in[13];
    const float* bo     = (const float*)d_in[14];
    const float* ln1w   = (const float*)d_in[15];
    const float* ln1b   = (const float*)d_in[16];
    const float* ln2w   = (const float*)d_in[17];
    const float* ln2b   = (const float*)d_in[18];
    const float* ffw1   = (const float*)d_in[19];
    const float* ffb1   = (const float*)d_in[20];
    const float* ffw2   = (const float*)d_in[21];
    const float* ffb2   = (const float*)d_in[22];

    static float *p_x = nullptr, *p_xn, *p_q, *p_k, *p_v, *p_tmp, *p_hg, *p_t;
    if (!p_x) {
        cudaGetSymbolAddress((void**)&p_x,   g_x);
        cudaGetSymbolAddress((void**)&p_xn,  g_xn);
        cudaGetSymbolAddress((void**)&p_q,   g_q);
        cudaGetSymbolAddress((void**)&p_k,   g_k);
        cudaGetSymbolAddress((void**)&p_v,   g_v);
        cudaGetSymbolAddress((void**)&p_tmp, g_tmp);
        cudaGetSymbolAddress((void**)&p_hg,  g_hg);
        cudaGetSymbolAddress((void**)&p_t,   g_t);
    }

    const int ROWS = BB * NN;   // 1024

    k_copy_in<<<ROWS, 256>>>(x);
    k_valid_ls<<<BB, NN>>>(x, coords);
    k_adj<<<BB, NN>>>(coords);

    for (int l = 0; l < LL; l++) {
        const float* Wq_l   = Wq   + (size_t)l * DD * INNER;
        const float* Wk_l   = Wk   + (size_t)l * DD * INNER;
        const float* Wv_l   = Wv   + (size_t)l * DD * INNER;
        const float* ebw1_l = ebw1 + (size_t)l * 11 * INNER;
        const float* ebb1_l = ebb1 + (size_t)l * INNER;
        const float* ebw2_l = ebw2 + (size_t)l * INNER * HH;
        const float* ebb2_l = ebb2 + (size_t)l * HH;
        const float* evw1_l = evw1 + (size_t)l * 11 * INNER;
        const float* evb1_l = evb1 + (size_t)l * INNER;
        const float* evw2_l = evw2 + (size_t)l * INNER * INNER;
        const float* evb2_l = evb2 + (size_t)l * INNER;
        const float* Wo_l   = Wo   + (size_t)l * INNER * DD;
        const float* bo_l   = bo   + (size_t)l * DD;
        const float* ln1w_l = ln1w + (size_t)l * DD;
        const float* ln1b_l = ln1b + (size_t)l * DD;
        const float* ln2w_l = ln2w + (size_t)l * DD;
        const float* ln2b_l = ln2b + (size_t)l * DD;
        const float* ffw1_l = ffw1 + (size_t)l * DD * FFH;
        const float* ffb1_l = ffb1 + (size_t)l * FFH;
        const float* ffw2_l = ffw2 + (size_t)l * FFHALF * DD;
        const float* ffb2_l = ffb2 + (size_t)l * DD;

        // xn = LN1(x)
        k_layernorm<<<ROWS, 256>>>(p_x, ln1w_l, ln1b_l, p_xn);
        // q,k,v
        k_gemm<<<dim3(INNER / 64, ROWS / 64), 256>>>(p_xn, Wq_l, nullptr, nullptr, p_q, ROWS, INNER, DD);
        k_gemm<<<dim3(INNER / 64, ROWS / 64), 256>>>(p_xn, Wk_l, nullptr, nullptr, p_k, ROWS, INNER, DD);
        k_gemm<<<dim3(INNER / 64, ROWS / 64), 256>>>(p_xn, Wv_l, nullptr, nullptr, p_v, ROWS, INNER, DD);
        // eb per adjacent edge
        k_eb<<<(BB * NN * NN * 32) / 256, 256>>>(coords, ebw1_l, ebb1_l, ebw2_l, ebb2_l);
        // attention
        k_attn<<<BB * HH * NN, 256>>>();
        k_outv<<<BB * HH * NN, 64>>>();
        // attn-weighted edge hidden
        k_Ag<<<BB * NN, 256>>>(coords, evw1_l, evb1_l);
        k_combine<<<BB * NN, 256>>>(evw2_l, evb2_l);
        // x += tmp @ Wo + bo
        k_gemm<<<dim3(DD / 64, ROWS / 64), 256>>>(p_tmp, Wo_l, bo_l, p_x, p_x, ROWS, DD, INNER);
        // FF block
        k_layernorm<<<ROWS, 256>>>(p_x, ln2w_l, ln2b_l, p_xn);
        k_gemm<<<dim3(FFH / 64, ROWS / 64), 256>>>(p_xn, ffw1_l, ffb1_l, nullptr, p_hg, ROWS, FFH, DD);
        k_glu<<<(ROWS * FFHALF) / 256, 256>>>();
        k_gemm<<<dim3(DD / 64, ROWS / 64), 256>>>(p_t, ffw2_l, ffb2_l, p_x, p_x, ROWS, DD, FFHALF);
    }

    k_copy_out<<<ROWS, 256>>>((float*)d_out);
}

// round 2
// speedup vs baseline: 1.1651x; 1.1651x over previous
#include <cuda_runtime.h>
#include <math.h>
#include <float.h>

// Problem constants
#define BB 4
#define NN 256
#define DD 256
#define HH 4
#define DH 64
#define INNER 256
#define LL 2
#define FFH 1024
#define FFHALF 512

// ---------------- device scratch ----------------
__device__ float g_x   [BB*NN*DD];
__device__ float g_xn  [BB*NN*DD];
__device__ float g_qkv [BB*NN*768];          // [row][q|k|v]
__device__ float g_wqkv[LL*DD*768];          // packed per-layer [k][q|k|v]
__device__ float g_eb  [BB*NN*NN*HH];
__device__ float g_attn[BB*HH*NN*NN];
__device__ float g_Ag  [HH*BB*NN*INNER];     // per-head planes
__device__ float g_tmp [BB*NN*INNER];
__device__ float g_hg  [BB*NN*FFH];
__device__ unsigned char g_adj[BB*NN*NN];
__device__ int   g_valid[BB*NN];
__device__ float g_ls[BB];

__device__ __forceinline__ float gelu_f(float x) {
    return 0.5f * x * (1.0f + erff(x * 0.70710678118654752440f));
}
__device__ __forceinline__ int hop_of(int n) {
    return (n == 0) ? 0 : ((n < 128) ? 1 : 2);
}
__device__ __forceinline__ float wredsum(float v) {
#pragma unroll
    for (int o = 16; o; o >>= 1) v += __shfl_xor_sync(0xffffffffu, v, o);
    return v;
}
__device__ __forceinline__ float wredmax(float v) {
#pragma unroll
    for (int o = 16; o; o >>= 1) v = fmaxf(v, __shfl_xor_sync(0xffffffffu, v, o));
    return v;
}

// ---------------- copy in/out ----------------
__global__ void k_copy_in(const float* __restrict__ src) {
    int i = blockIdx.x * blockDim.x + threadIdx.x;
    g_x[i] = src[i];
}
__global__ void k_copy_out(float* __restrict__ dst) {
    int i = blockIdx.x * blockDim.x + threadIdx.x;
    dst[i] = g_x[i];
}

// ---------------- pack QKV weights: g_wqkv[l][k][z*256+n] ----------------
__global__ void k_pack(const float* __restrict__ Wq, const float* __restrict__ Wk,
                       const float* __restrict__ Wv) {
    int idx = blockIdx.x * blockDim.x + threadIdx.x;    // < LL*256*768
    int l = idx / (DD * 768);
    int rem = idx % (DD * 768);
    int k = rem / 768, c = rem % 768;
    int z = c >> 8, n = c & 255;
    const float* src = (z == 0) ? Wq : ((z == 1) ? Wk : Wv);
    g_wqkv[idx] = src[(size_t)l * DD * INNER + k * INNER + n];
}

// ---------------- graph build ----------------
__global__ void k_valid_ls(const float* __restrict__ x, const float* __restrict__ coords) {
    int b = blockIdx.x, n = threadIdx.x;
    const float* xr = x + (size_t)(b * NN + n) * DD;
    float s = 0.f;
    for (int d = 0; d < DD; d++) s += fabsf(xr[d]);
    int val = (s > 0.f) || (n == 0);
    g_valid[b * NN + n] = val;
    float cx = coords[(b * NN + n) * 2 + 0];
    float cy = coords[(b * NN + n) * 2 + 1];
    float cd = sqrtf(cx * cx + cy * cy + 1e-8f);
    int nvm = val && (n > 0);
    __shared__ float sd8[8], sc8[8];
    float vs = nvm ? cd : 0.f, vc = nvm ? 1.f : 0.f;
    float ws = wredsum(vs), wc = wredsum(vc);
    if ((n & 31) == 0) { sd8[n >> 5] = ws; sc8[n >> 5] = wc; }
    __syncthreads();
    if (n == 0) {
        float tS = 0.f, tC = 0.f;
#pragma unroll
        for (int k = 0; k < 8; k++) { tS += sd8[k]; tC += sc8[k]; }
        float cnt = fmaxf(tC, 1.f);
        float ls = tS / cnt;
        g_ls[b] = (ls > 0.f) ? ls : 1.f;
    }
}

__global__ void k_adj(const float* __restrict__ coords) {
    int b = blockIdx.x, i = threadIdx.x;
    int vi = g_valid[b * NN + i];
    unsigned char* row = g_adj + (size_t)(b * NN + i) * NN;
    for (int j = 0; j < NN; j++) {
        int vj = g_valid[b * NN + j];
        int a = (i == j);
        if (i == 0 && j > 0) a |= vj;
        if (j == 0 && i > 0) a |= vi;
        row[j] = (unsigned char)a;
    }
    __syncthreads();
    if (i >= 1 && vi) {
        float cix = coords[(b * NN + i) * 2 + 0];
        float ciy = coords[(b * NN + i) * 2 + 1];
        float bd0 = FLT_MAX, bd1 = FLT_MAX, bd2 = FLT_MAX;
        int   bi0 = -1, bi1 = -1, bi2 = -1;
        for (int j = 1; j < NN; j++) {
            if (j == i) continue;
            if (!g_valid[b * NN + j]) continue;
            float dx = coords[(b * NN + j) * 2 + 0] - cix;
            float dy = coords[(b * NN + j) * 2 + 1] - ciy;
            float d2 = dx * dx + dy * dy;
            if (d2 < bd0)      { bd2 = bd1; bi2 = bi1; bd1 = bd0; bi1 = bi0; bd0 = d2; bi0 = j; }
            else if (d2 < bd1) { bd2 = bd1; bi2 = bi1; bd1 = d2; bi1 = j; }
            else if (d2 < bd2) { bd2 = d2; bi2 = j; }
        }
        if (bi0 >= 0) { g_adj[(b * NN + i) * NN + bi0] = 1; g_adj[(b * NN + bi0) * NN + i] = 1; }
        if (bi1 >= 0) { g_adj[(b * NN + i) * NN + bi1] = 1; g_adj[(b * NN + bi1) * NN + i] = 1; }
        if (bi2 >= 0) { g_adj[(b * NN + i) * NN + bi2] = 1; g_adj[(b * NN + bi2) * NN + i] = 1; }
    }
}

// ---------------- layernorm (shuffle) ----------------
__global__ void __launch_bounds__(256) k_layernorm(const float* __restrict__ x,
                            const float* __restrict__ w,
                            const float* __restrict__ bia, float* __restrict__ out) {
    int row = blockIdx.x, t = threadIdx.x;
    float v = x[(size_t)row * DD + t];
    __shared__ float s8[8];
    float ws = wredsum(v);
    if ((t & 31) == 0) s8[t >> 5] = ws;
    __syncthreads();
    float mean = 0.f;
#pragma unroll
    for (int k = 0; k < 8; k++) mean += s8[k];
    mean *= (1.f / DD);
    float d = v - mean;
    __syncthreads();
    ws = wredsum(d * d);
    if ((t & 31) == 0) s8[t >> 5] = ws;
    __syncthreads();
    float var = 0.f;
#pragma unroll
    for (int k = 0; k < 8; k++) var += s8[k];
    var *= (1.f / DD);
    out[(size_t)row * DD + t] = d * rsqrtf(var + 1e-5f) * w[t] + bia[t];
}

// ---------------- tiled GEMM, 64x64 per block, 4x4 per thread, conflict-free ----------------
template<bool GLU, bool HASBIAS, bool HASRES>
__global__ void __launch_bounds__(256) k_gemm2(
    const float* __restrict__ A, const float* __restrict__ W,
    const float* __restrict__ bias, const float* __restrict__ resid,
    float* __restrict__ C,
    int K, int lda, int ldw, int ldc,
    long aStrideZ, long wStrideZ, long cStrideZ, int biasStrideZ)
{
    __shared__ float Ast[16][68];   // [kk][m], padded
    __shared__ float Ws [16][68];   // [kk][n], padded
    int z = blockIdx.z;
    A += (long)z * aStrideZ;
    W += (long)z * wStrideZ;
    C += (long)z * cStrideZ;
    const float* Rp = resid;
    if (HASRES) Rp += (long)z * cStrideZ;
    const float* Bp = bias;
    if (HASBIAS) Bp += (long)z * biasStrideZ;

    int bm = blockIdx.y, bn = blockIdx.x;
    int tid = threadIdx.x;
    int ty = tid >> 4, tx = tid & 15;
    int arow = tid >> 2, ak4 = (tid & 3) * 4;
    int wkk = tid >> 4, wn4 = (tid & 15) * 4;

    float acc[4][4] = {};
    for (int kt = 0; kt < K; kt += 16) {
        const float* Aptr = A + (size_t)(bm * 64 + arow) * lda + kt + ak4;
        float4 a4;
        if (GLU) {
            float4 av = *(const float4*)Aptr;
            float4 gv = *(const float4*)(Aptr + FFHALF);
            a4.x = av.x * gelu_f(gv.x);
            a4.y = av.y * gelu_f(gv.y);
            a4.z = av.z * gelu_f(gv.z);
            a4.w = av.w * gelu_f(gv.w);
        } else {
            a4 = *(const float4*)Aptr;
        }
        float4 w4 = *(const float4*)(W + (size_t)(kt + wkk) * ldw + bn * 64 + wn4);
        Ast[ak4 + 0][arow] = a4.x;
        Ast[ak4 + 1][arow] = a4.y;
        Ast[ak4 + 2][arow] = a4.z;
        Ast[ak4 + 3][arow] = a4.w;
        *(float4*)&Ws[wkk][wn4] = w4;
        __syncthreads();
#pragma unroll
        for (int kk = 0; kk < 16; kk++) {
            float4 a = *(const float4*)&Ast[kk][ty * 4];
            float4 w = *(const float4*)&Ws[kk][tx * 4];
            acc[0][0] += a.x * w.x; acc[0][1] += a.x * w.y; acc[0][2] += a.x * w.z; acc[0][3] += a.x * w.w;
            acc[1][0] += a.y * w.x; acc[1][1] += a.y * w.y; acc[1][2] += a.y * w.z; acc[1][3] += a.y * w.w;
            acc[2][0] += a.z * w.x; acc[2][1] += a.z * w.y; acc[2][2] += a.z * w.z; acc[2][3] += a.z * w.w;
            acc[3][0] += a.w * w.x; acc[3][1] += a.w * w.y; acc[3][2] += a.w * w.z; acc[3][3] += a.w * w.w;
        }
        __syncthreads();
    }
    int row0 = bm * 64 + ty * 4;
    int col  = bn * 64 + tx * 4;
    float4 bb = make_float4(0.f, 0.f, 0.f, 0.f);
    if (HASBIAS) bb = *(const float4*)&Bp[col];
#pragma unroll
    for (int r = 0; r < 4; r++) {
        float4 v = make_float4(acc[r][0] + bb.x, acc[r][1] + bb.y,
                               acc[r][2] + bb.z, acc[r][3] + bb.w);
        if (HASRES) {
            float4 rr = *(const float4*)&Rp[(size_t)(row0 + r) * ldc + col];
            v.x += rr.x; v.y += rr.y; v.z += rr.z; v.w += rr.w;
        }
        *(float4*)&C[(size_t)(row0 + r) * ldc + col] = v;
    }
}

// ---------------- eb: per adjacent edge MLP -> 4 heads ----------------
__global__ void k_eb(const float* __restrict__ coords,
                     const float* __restrict__ w1, const float* __restrict__ b1,
                     const float* __restrict__ w2, const float* __restrict__ b2) {
    int gw = (blockIdx.x * blockDim.x + threadIdx.x) >> 5;
    int lane = threadIdx.x & 31;
    if (gw >= BB * NN * NN) return;
    if (!g_adj[gw]) return;
    int b = gw >> 16, i = (gw >> 8) & 255, j = gw & 255;
    float invls = 1.f / fmaxf(g_ls[b], 1e-6f);
    float cix = coords[(b * NN + i) * 2 + 0], ciy = coords[(b * NN + i) * 2 + 1];
    float cjx = coords[(b * NN + j) * 2 + 0], cjy = coords[(b * NN + j) * 2 + 1];
    float f[10];
    float dx = cjx - cix, dy = cjy - ciy;
    float dist = sqrtf(dx * dx + dy * dy + 1e-8f);
    f[0] = dx; f[1] = dy; f[2] = dist; f[3] = dist * invls;
    f[4] = (i == 0) ? 1.f : 0.f;
    f[5] = (j == 0) ? 1.f : 0.f;
    f[6] = (i == j) ? 1.f : 0.f;
    f[7] = ((i != 0) && (j != 0) && (i != j)) ? 1.f : 0.f;
    int hi = hop_of(i), hj = hop_of(j);
    f[8] = (hi == hj) ? 1.f : 0.f;
    f[9] = fabsf((float)(hj - hi));
    float a0 = 0, a1 = 0, a2 = 0, a3 = 0;
#pragma unroll
    for (int t = 0; t < 8; t++) {
        int m = t * 32 + lane;
        float h = b1[m];
#pragma unroll
        for (int q = 0; q < 10; q++) h += f[q] * w1[q * INNER + m];
        h = gelu_f(h);
        a0 += h * w2[m * 4 + 0];
        a1 += h * w2[m * 4 + 1];
        a2 += h * w2[m * 4 + 2];
        a3 += h * w2[m * 4 + 3];
    }
    a0 = wredsum(a0); a1 = wredsum(a1); a2 = wredsum(a2); a3 = wredsum(a3);
    if (lane == 0) {
        float* o = g_eb + (size_t)gw * 4;
        o[0] = a0 + b2[0];
        o[1] = a1 + b2[1];
        o[2] = a2 + b2[2];
        o[3] = a3 + b2[3];
    }
}

// ---------------- attention: scores + softmax + out_v (into g_tmp) ----------------
__global__ void __launch_bounds__(256) k_attn() {
    int blk = blockIdx.x;                 // b*1024 + h*256 + i
    int j = threadIdx.x;
    int i = blk & 255, h = (blk >> 8) & 3, b = blk >> 10;
    __shared__ float qs[DH];
    __shared__ float sp[NN];
    __shared__ float s8[8];
    if (j < DH) qs[j] = g_qkv[(size_t)(b * NN + i) * 768 + h * DH + j];
    __syncthreads();
    int adj = g_adj[(b * NN + i) * NN + j];
    float sim = -FLT_MAX;
    if (adj) {
        const float* kr = g_qkv + (size_t)(b * NN + j) * 768 + 256 + h * DH;
        float d = 0.f;
#pragma unroll
        for (int t = 0; t < DH; t++) d += qs[t] * kr[t];
        sim = d * 0.125f + g_eb[((size_t)(b * NN + i) * NN + j) * 4 + h];
    }
    float wm = wredmax(sim);
    if ((j & 31) == 0) s8[j >> 5] = wm;
    __syncthreads();
    float mx = s8[0];
#pragma unroll
    for (int k = 1; k < 8; k++) mx = fmaxf(mx, s8[k]);
    float ex = adj ? expf(sim - mx) : 0.f;
    __syncthreads();
    float wsum = wredsum(ex);
    if ((j & 31) == 0) s8[j >> 5] = wsum;
    __syncthreads();
    float tot = 0.f;
#pragma unroll
    for (int k = 0; k < 8; k++) tot += s8[k];
    float p = ex / tot;
    sp[j] = p;
    g_attn[((size_t)(b * HH + h) * NN + i) * NN + j] = p;
    __syncthreads();
    // out_v: thread t -> d = t&63, chunk = t>>6
    int d = j & 63, c0 = (j >> 6) * 64;
    float acc = 0.f;
    for (int jj = c0; jj < c0 + 64; jj++) {
        float pv = sp[jj];
        if (pv != 0.f)
            acc += pv * g_qkv[(size_t)(b * NN + jj) * 768 + 512 + h * DH + d];
    }
    __syncthreads();
    sp[j] = acc;
    __syncthreads();
    if (j < 64)
        g_tmp[(size_t)(b * NN + i) * INNER + h * DH + j] =
            sp[j] + sp[64 + j] + sp[128 + j] + sp[192 + j];
}

// ---------------- A_g = sum_j attn * gelu(e@ev_w1+b1), per-head planes ----------------
__global__ void __launch_bounds__(256) k_Ag(const float* __restrict__ coords,
                     const float* __restrict__ w1, const float* __restrict__ b1) {
    int b = blockIdx.x >> 8, i = blockIdx.x & 255, m = threadIdx.x;
    __shared__ float sa[HH][NN];
    __shared__ float scx[NN], scy[NN];
    __shared__ unsigned char sadj[NN];
#pragma unroll
    for (int h = 0; h < HH; h++)
        sa[h][m] = g_attn[((size_t)(b * HH + h) * NN + i) * NN + m];
    sadj[m] = g_adj[(b * NN + i) * NN + m];
    scx[m] = coords[(b * NN + m) * 2 + 0];
    scy[m] = coords[(b * NN + m) * 2 + 1];
    __syncthreads();
    float w1r[10];
#pragma unroll
    for (int f = 0; f < 10; f++) w1r[f] = w1[f * INNER + m];
    float b1m = b1[m];
    float invls = 1.f / fmaxf(g_ls[b], 1e-6f);
    float cix = scx[i], ciy = scy[i];
    int hi = hop_of(i);
    float qic = (i == 0) ? 1.f : 0.f;
    float acc0 = 0, acc1 = 0, acc2 = 0, acc3 = 0;
    for (int j = 0; j < NN; j++) {
        if (!sadj[j]) continue;
        float dx = scx[j] - cix, dy = scy[j] - ciy;
        float dist = sqrtf(dx * dx + dy * dy + 1e-8f);
        float kic = (j == 0) ? 1.f : 0.f;
        float ey = (i == j) ? 1.f : 0.f;
        float isnn = ((i != 0) && (j != 0) && (i != j)) ? 1.f : 0.f;
        int hj = hop_of(j);
        float hv = b1m + dx * w1r[0] + dy * w1r[1] + dist * w1r[2]
                 + (dist * invls) * w1r[3] + qic * w1r[4] + kic * w1r[5]
                 + ey * w1r[6] + isnn * w1r[7]
                 + ((hi == hj) ? 1.f : 0.f) * w1r[8]
                 + fabsf((float)(hj - hi)) * w1r[9];
        hv = gelu_f(hv);
        acc0 += sa[0][j] * hv;
        acc1 += sa[1][j] * hv;
        acc2 += sa[2][j] * hv;
        acc3 += sa[3][j] * hv;
    }
    size_t base = (size_t)(b * NN + i) * INNER + m;
    g_Ag[0 * (size_t)(BB * NN * INNER) + base] = acc0;
    g_Ag[1 * (size_t)(BB * NN * INNER) + base] = acc1;
    g_Ag[2 * (size_t)(BB * NN * INNER) + base] = acc2;
    g_Ag[3 * (size_t)(BB * NN * INNER) + base] = acc3;
}

// ---------------- host launch ----------------
extern "C" void kernel_launch(void* const* d_in, const int* in_sizes, int n_in,
                              void* d_out, int out_size) {
    const float* x      = (const float*)d_in[0];
    const float* coords = (const float*)d_in[1];
    const float* Wq     = (const float*)d_in[2];
    const float* Wk     = (const float*)d_in[3];
    const float* Wv     = (const float*)d_in[4];
    const float* ebw1   = (const float*)d_in[5];
    const float* ebb1   = (const float*)d_in[6];
    const float* ebw2   = (const float*)d_in[7];
    const float* ebb2   = (const float*)d_in[8];
    const float* evw1   = (const float*)d_in[9];
    const float* evb1   = (const float*)d_in[10];
    const float* evw2   = (const float*)d_in[11];
    const float* evb2   = (const float*)d_in[12];
    const float* Wo     = (const float*)d_in[13];
    const float* bo     = (const float*)d_in[14];
    const float* ln1w   = (const float*)d_in[15];
    const float* ln1b   = (const float*)d_in[16];
    const float* ln2w   = (const float*)d_in[17];
    const float* ln2b   = (const float*)d_in[18];
    const float* ffw1   = (const float*)d_in[19];
    const float* ffb1   = (const float*)d_in[20];
    const float* ffw2   = (const float*)d_in[21];
    const float* ffb2   = (const float*)d_in[22];

    static float *p_x = nullptr, *p_xn, *p_qkv, *p_wqkv, *p_tmp, *p_hg, *p_Ag;
    if (!p_x) {
        cudaGetSymbolAddress((void**)&p_x,    g_x);
        cudaGetSymbolAddress((void**)&p_xn,   g_xn);
        cudaGetSymbolAddress((void**)&p_qkv,  g_qkv);
        cudaGetSymbolAddress((void**)&p_wqkv, g_wqkv);
        cudaGetSymbolAddress((void**)&p_tmp,  g_tmp);
        cudaGetSymbolAddress((void**)&p_hg,   g_hg);
        cudaGetSymbolAddress((void**)&p_Ag,   g_Ag);
    }

    const int ROWS = BB * NN;   // 1024

    k_copy_in<<<ROWS, 256>>>(x);
    k_pack<<<(LL * DD * 768) / 256, 256>>>(Wq, Wk, Wv);
    k_valid_ls<<<BB, NN>>>(x, coords);
    k_adj<<<BB, NN>>>(coords);

    for (int l = 0; l < LL; l++) {
        const float* ebw1_l = ebw1 + (size_t)l * 11 * INNER;
        const float* ebb1_l = ebb1 + (size_t)l * INNER;
        const float* ebw2_l = ebw2 + (size_t)l * INNER * HH;
        const float* ebb2_l = ebb2 + (size_t)l * HH;
        const float* evw1_l = evw1 + (size_t)l * 11 * INNER;
        const float* evb1_l = evb1 + (size_t)l * INNER;
        const float* evw2_l = evw2 + (size_t)l * INNER * INNER;
        const float* evb2_l = evb2 + (size_t)l * INNER;
        const float* Wo_l   = Wo   + (size_t)l * INNER * DD;
        const float* bo_l   = bo   + (size_t)l * DD;
        const float* ffw1_l = ffw1 + (size_t)l * DD * FFH;
        const float* ffb1_l = ffb1 + (size_t)l * FFH;
        const float* ffw2_l = ffw2 + (size_t)l * FFHALF * DD;
        const float* ffb2_l = ffb2 + (size_t)l * DD;

        // xn = LN1(x)
        k_layernorm<<<ROWS, 256>>>(p_x, ln1w + l * DD, ln1b + l * DD, p_xn);
        // fused QKV: [1024,256] @ [256,768]
        k_gemm2<false, false, false><<<dim3(768 / 64, ROWS / 64, 1), 256>>>(
            p_xn, p_wqkv + (size_t)l * DD * 768, nullptr, nullptr, p_qkv,
            DD, DD, 768, 768, 0, 0, 0, 0);
        // eb per adjacent edge
        k_eb<<<(BB * NN * NN * 32) / 256, 256>>>(coords, ebw1_l, ebb1_l, ebw2_l, ebb2_l);
        // attention + out_v (out_v lands in g_tmp)
        k_attn<<<BB * HH * NN, 256>>>();
        // attn-weighted edge hidden
        k_Ag<<<BB * NN, 256>>>(coords, evw1_l, evb1_l);
        // combine: per-head GEMM  tmp[:, h*64:(h+1)*64] += Ag_h @ evw2[:, h*64:] + evb2
        k_gemm2<false, true, true><<<dim3(1, ROWS / 64, HH), 256>>>(
            p_Ag, evw2_l, evb2_l, p_tmp, p_tmp,
            INNER, INNER, INNER, INNER,
            (long)BB * NN * INNER, 64, 64, 64);
        // x += tmp @ Wo + bo
        k_gemm2<false, true, true><<<dim3(DD / 64, ROWS / 64, 1), 256>>>(
            p_tmp, Wo_l, bo_l, p_x, p_x,
            INNER, INNER, DD, DD, 0, 0, 0, 0);
        // FF block
        k_layernorm<<<ROWS, 256>>>(p_x, ln2w + l * DD, ln2b + l * DD, p_xn);
        k_gemm2<false, true, false><<<dim3(FFH / 64, ROWS / 64, 1), 256>>>(
            p_xn, ffw1_l, ffb1_l, nullptr, p_hg,
            DD, DD, FFH, FFH, 0, 0, 0, 0);
        // x += (a * gelu(g)) @ ffw2 + ffb2   (GLU fused into A-load)
        k_gemm2<true, true, true><<<dim3(DD / 64, ROWS / 64, 1), 256>>>(
            p_hg, ffw2_l, ffb2_l, p_x, p_x,
            FFHALF, FFH, DD, DD, 0, 0, 0, 0);
    }

    k_copy_out<<<ROWS, 256>>>((float*)d_out);
}

// round 3
// speedup vs baseline: 1.3991x; 1.2008x over previous
#include <cuda_runtime.h>
#include <math.h>
#include <float.h>

// Problem constants
#define BB 4
#define NN 256
#define DD 256
#define HH 4
#define DH 64
#define INNER 256
#define LL 2
#define FFH 1024
#define FFHALF 512
#define MAXE (BB*NN*16)

// ---------------- device scratch ----------------
__device__ float g_x   [BB*NN*DD];
__device__ float g_xn  [BB*NN*DD];
__device__ float g_qkv [BB*NN*768];          // [row][q|k|v]
__device__ float g_wqkv[LL*DD*768];          // packed per-layer [k][q|k|v]
__device__ float g_eb  [BB*NN*NN*HH];
__device__ float g_attn[BB*HH*NN*NN];
__device__ float g_Ag  [HH*BB*NN*INNER];     // per-head planes
__device__ float g_tmp [BB*NN*INNER];
__device__ float g_hg  [BB*NN*FFH];
__device__ unsigned char g_adj[BB*NN*NN];
__device__ int   g_valid[BB*NN];
__device__ float g_ls[BB];
__device__ int   g_elist[MAXE];
__device__ int   g_ecnt;

__device__ __forceinline__ float gelu_f(float x) {
    return 0.5f * x * (1.0f + erff(x * 0.70710678118654752440f));
}
__device__ __forceinline__ int hop_of(int n) {
    return (n == 0) ? 0 : ((n < 128) ? 1 : 2);
}
__device__ __forceinline__ float wredsum(float v) {
#pragma unroll
    for (int o = 16; o; o >>= 1) v += __shfl_xor_sync(0xffffffffu, v, o);
    return v;
}
__device__ __forceinline__ float wredmax(float v) {
#pragma unroll
    for (int o = 16; o; o >>= 1) v = fmaxf(v, __shfl_xor_sync(0xffffffffu, v, o));
    return v;
}

// ---------------- copy in/out ----------------
__global__ void k_copy_in(const float* __restrict__ src) {
    int i = blockIdx.x * blockDim.x + threadIdx.x;
    ((float4*)g_x)[i] = ((const float4*)src)[i];
}
__global__ void k_copy_out(float* __restrict__ dst) {
    int i = blockIdx.x * blockDim.x + threadIdx.x;
    ((float4*)dst)[i] = ((const float4*)g_x)[i];
}

// ---------------- pack QKV weights ----------------
__global__ void k_pack(const float* __restrict__ Wq, const float* __restrict__ Wk,
                       const float* __restrict__ Wv) {
    int idx = blockIdx.x * blockDim.x + threadIdx.x;    // < LL*256*768
    int l = idx / (DD * 768);
    int rem = idx % (DD * 768);
    int k = rem / 768, c = rem % 768;
    int z = c >> 8, n = c & 255;
    const float* src = (z == 0) ? Wq : ((z == 1) ? Wk : Wv);
    g_wqkv[idx] = src[(size_t)l * DD * INNER + k * INNER + n];
}

// ---------------- validity: one block per row, coalesced ----------------
__global__ void __launch_bounds__(256) k_valid(const float* __restrict__ x) {
    int row = blockIdx.x, t = threadIdx.x;
    float v = fabsf(x[(size_t)row * DD + t]);
    __shared__ float s8[8];
    float ws = wredsum(v);
    if ((t & 31) == 0) s8[t >> 5] = ws;
    __syncthreads();
    if (t == 0) {
        float s = 0.f;
#pragma unroll
        for (int k = 0; k < 8; k++) s += s8[k];
        int n = row & 255;
        g_valid[row] = (s > 0.f) || (n == 0);
        if (row == 0) g_ecnt = 0;
    }
}

__global__ void k_ls(const float* __restrict__ coords) {
    int b = blockIdx.x, n = threadIdx.x;
    float cx = coords[(b * NN + n) * 2 + 0];
    float cy = coords[(b * NN + n) * 2 + 1];
    float cd = sqrtf(cx * cx + cy * cy + 1e-8f);
    int nvm = g_valid[b * NN + n] && (n > 0);
    __shared__ float sd8[8], sc8[8];
    float ws = wredsum(nvm ? cd : 0.f), wc = wredsum(nvm ? 1.f : 0.f);
    if ((n & 31) == 0) { sd8[n >> 5] = ws; sc8[n >> 5] = wc; }
    __syncthreads();
    if (n == 0) {
        float tS = 0.f, tC = 0.f;
#pragma unroll
        for (int k = 0; k < 8; k++) { tS += sd8[k]; tC += sc8[k]; }
        float ls = tS / fmaxf(tC, 1.f);
        g_ls[b] = (ls > 0.f) ? ls : 1.f;
    }
}

// ---------------- adjacency + KNN + edge list, all from smem ----------------
__global__ void __launch_bounds__(256) k_adj(const float* __restrict__ coords) {
    int b = blockIdx.x, i = threadIdx.x;
    __shared__ float scx[NN], scy[NN];
    __shared__ int sval[NN];
    sval[i] = g_valid[b * NN + i];
    scx[i] = coords[(b * NN + i) * 2 + 0];
    scy[i] = coords[(b * NN + i) * 2 + 1];
    __syncthreads();
    int vi = sval[i];
    unsigned* row32 = (unsigned*)(g_adj + (size_t)(b * NN + i) * NN);
#pragma unroll 4
    for (int j4 = 0; j4 < 64; j4++) {
        unsigned v = 0;
#pragma unroll
        for (int u = 0; u < 4; u++) {
            int j = j4 * 4 + u;
            int a = (i == j);
            if (i == 0 && j > 0) a |= (sval[j] != 0);
            if (j == 0 && i > 0) a |= (vi != 0);
            v |= ((unsigned)a) << (8 * u);
        }
        row32[j4] = v;
    }
    __syncthreads();
    if (i >= 1 && vi) {
        float cix = scx[i], ciy = scy[i];
        float bd0 = FLT_MAX, bd1 = FLT_MAX, bd2 = FLT_MAX;
        int   bi0 = -1, bi1 = -1, bi2 = -1;
        for (int j = 1; j < NN; j++) {
            if (j == i || !sval[j]) continue;
            float dx = scx[j] - cix, dy = scy[j] - ciy;
            float d2 = dx * dx + dy * dy;
            if (d2 < bd0)      { bd2 = bd1; bi2 = bi1; bd1 = bd0; bi1 = bi0; bd0 = d2; bi0 = j; }
            else if (d2 < bd1) { bd2 = bd1; bi2 = bi1; bd1 = d2; bi1 = j; }
            else if (d2 < bd2) { bd2 = d2; bi2 = j; }
        }
        if (bi0 >= 0) { g_adj[(size_t)(b * NN + i) * NN + bi0] = 1; g_adj[(size_t)(b * NN + bi0) * NN + i] = 1; }
        if (bi1 >= 0) { g_adj[(size_t)(b * NN + i) * NN + bi1] = 1; g_adj[(size_t)(b * NN + bi1) * NN + i] = 1; }
        if (bi2 >= 0) { g_adj[(size_t)(b * NN + i) * NN + bi2] = 1; g_adj[(size_t)(b * NN + bi2) * NN + i] = 1; }
    }
    __syncthreads();
    // edge list: count row edges, one atomic per thread, then write indices
    const unsigned char* row = g_adj + (size_t)(b * NN + i) * NN;
    int cnt = 0;
    for (int j = 0; j < NN; j++) cnt += row[j] ? 1 : 0;
    int off = atomicAdd(&g_ecnt, cnt);
    int base = (b << 16) | (i << 8);
    for (int j = 0; j < NN; j++)
        if (row[j]) g_elist[off++] = base | j;
}

// ---------------- layernorm (shuffle) ----------------
__global__ void __launch_bounds__(256) k_layernorm(const float* __restrict__ x,
                            const float* __restrict__ w,
                            const float* __restrict__ bia, float* __restrict__ out) {
    int row = blockIdx.x, t = threadIdx.x;
    float v = x[(size_t)row * DD + t];
    __shared__ float s8[8];
    float ws = wredsum(v);
    if ((t & 31) == 0) s8[t >> 5] = ws;
    __syncthreads();
    float mean = 0.f;
#pragma unroll
    for (int k = 0; k < 8; k++) mean += s8[k];
    mean *= (1.f / DD);
    float d = v - mean;
    __syncthreads();
    ws = wredsum(d * d);
    if ((t & 31) == 0) s8[t >> 5] = ws;
    __syncthreads();
    float var = 0.f;
#pragma unroll
    for (int k = 0; k < 8; k++) var += s8[k];
    var *= (1.f / DD);
    out[(size_t)row * DD + t] = d * rsqrtf(var + 1e-5f) * w[t] + bia[t];
}

// ---------------- tiled GEMM, 64x64 per block, 4x4 per thread ----------------
template<bool GLU, bool HASBIAS, bool HASRES>
__global__ void __launch_bounds__(256) k_gemm2(
    const float* __restrict__ A, const float* __restrict__ W,
    const float* __restrict__ bias, const float* __restrict__ resid,
    float* __restrict__ C,
    int K, int lda, int ldw, int ldc,
    long aStrideZ, long wStrideZ, long cStrideZ, int biasStrideZ)
{
    __shared__ float Ast[16][68];
    __shared__ float Ws [16][68];
    int z = blockIdx.z;
    A += (long)z * aStrideZ;
    W += (long)z * wStrideZ;
    C += (long)z * cStrideZ;
    const float* Rp = resid;
    if (HASRES) Rp += (long)z * cStrideZ;
    const float* Bp = bias;
    if (HASBIAS) Bp += (long)z * biasStrideZ;

    int bm = blockIdx.y, bn = blockIdx.x;
    int tid = threadIdx.x;
    int ty = tid >> 4, tx = tid & 15;
    int arow = tid >> 2, ak4 = (tid & 3) * 4;
    int wkk = tid >> 4, wn4 = (tid & 15) * 4;

    float acc[4][4] = {};
    for (int kt = 0; kt < K; kt += 16) {
        const float* Aptr = A + (size_t)(bm * 64 + arow) * lda + kt + ak4;
        float4 a4;
        if (GLU) {
            float4 av = *(const float4*)Aptr;
            float4 gv = *(const float4*)(Aptr + FFHALF);
            a4.x = av.x * gelu_f(gv.x);
            a4.y = av.y * gelu_f(gv.y);
            a4.z = av.z * gelu_f(gv.z);
            a4.w = av.w * gelu_f(gv.w);
        } else {
            a4 = *(const float4*)Aptr;
        }
        float4 w4 = *(const float4*)(W + (size_t)(kt + wkk) * ldw + bn * 64 + wn4);
        Ast[ak4 + 0][arow] = a4.x;
        Ast[ak4 + 1][arow] = a4.y;
        Ast[ak4 + 2][arow] = a4.z;
        Ast[ak4 + 3][arow] = a4.w;
        *(float4*)&Ws[wkk][wn4] = w4;
        __syncthreads();
#pragma unroll
        for (int kk = 0; kk < 16; kk++) {
            float4 a = *(const float4*)&Ast[kk][ty * 4];
            float4 w = *(const float4*)&Ws[kk][tx * 4];
            acc[0][0] += a.x * w.x; acc[0][1] += a.x * w.y; acc[0][2] += a.x * w.z; acc[0][3] += a.x * w.w;
            acc[1][0] += a.y * w.x; acc[1][1] += a.y * w.y; acc[1][2] += a.y * w.z; acc[1][3] += a.y * w.w;
            acc[2][0] += a.z * w.x; acc[2][1] += a.z * w.y; acc[2][2] += a.z * w.z; acc[2][3] += a.z * w.w;
            acc[3][0] += a.w * w.x; acc[3][1] += a.w * w.y; acc[3][2] += a.w * w.z; acc[3][3] += a.w * w.w;
        }
        __syncthreads();
    }
    int row0 = bm * 64 + ty * 4;
    int col  = bn * 64 + tx * 4;
    float4 bb = make_float4(0.f, 0.f, 0.f, 0.f);
    if (HASBIAS) bb = *(const float4*)&Bp[col];
#pragma unroll
    for (int r = 0; r < 4; r++) {
        float4 v = make_float4(acc[r][0] + bb.x, acc[r][1] + bb.y,
                               acc[r][2] + bb.z, acc[r][3] + bb.w);
        if (HASRES) {
            float4 rr = *(const float4*)&Rp[(size_t)(row0 + r) * ldc + col];
            v.x += rr.x; v.y += rr.y; v.z += rr.z; v.w += rr.w;
        }
        *(float4*)&C[(size_t)(row0 + r) * ldc + col] = v;
    }
}

// ---------------- eb over compacted edge list ----------------
__global__ void k_eb(const float* __restrict__ coords,
                     const float* __restrict__ w1, const float* __restrict__ b1,
                     const float* __restrict__ w2, const float* __restrict__ b2) {
    int gwarp = blockIdx.x * (blockDim.x >> 5) + (threadIdx.x >> 5);
    int nwarp = gridDim.x * (blockDim.x >> 5);
    int lane = threadIdx.x & 31;
    int cnt = g_ecnt;
    for (int e = gwarp; e < cnt; e += nwarp) {
        int gw = g_elist[e];
        int b = gw >> 16, i = (gw >> 8) & 255, j = gw & 255;
        float invls = 1.f / fmaxf(g_ls[b], 1e-6f);
        float cix = coords[(b * NN + i) * 2 + 0], ciy = coords[(b * NN + i) * 2 + 1];
        float cjx = coords[(b * NN + j) * 2 + 0], cjy = coords[(b * NN + j) * 2 + 1];
        float f[10];
        float dx = cjx - cix, dy = cjy - ciy;
        float dist = sqrtf(dx * dx + dy * dy + 1e-8f);
        f[0] = dx; f[1] = dy; f[2] = dist; f[3] = dist * invls;
        f[4] = (i == 0) ? 1.f : 0.f;
        f[5] = (j == 0) ? 1.f : 0.f;
        f[6] = (i == j) ? 1.f : 0.f;
        f[7] = ((i != 0) && (j != 0) && (i != j)) ? 1.f : 0.f;
        int hi = hop_of(i), hj = hop_of(j);
        f[8] = (hi == hj) ? 1.f : 0.f;
        f[9] = fabsf((float)(hj - hi));
        float a0 = 0, a1 = 0, a2 = 0, a3 = 0;
#pragma unroll
        for (int t = 0; t < 8; t++) {
            int m = t * 32 + lane;
            float h = b1[m];
#pragma unroll
            for (int q = 0; q < 10; q++) h += f[q] * w1[q * INNER + m];
            h = gelu_f(h);
            a0 += h * w2[m * 4 + 0];
            a1 += h * w2[m * 4 + 1];
            a2 += h * w2[m * 4 + 2];
            a3 += h * w2[m * 4 + 3];
        }
        a0 = wredsum(a0); a1 = wredsum(a1); a2 = wredsum(a2); a3 = wredsum(a3);
        if (lane == 0) {
            float* o = g_eb + (size_t)((b * NN + i) * NN + j) * 4;
            o[0] = a0 + b2[0];
            o[1] = a1 + b2[1];
            o[2] = a2 + b2[2];
            o[3] = a3 + b2[3];
        }
    }
}

// ---------------- attention: scores + softmax + out_v ----------------
__global__ void __launch_bounds__(256) k_attn() {
    int blk = blockIdx.x;                 // b*1024 + h*256 + i
    int j = threadIdx.x;
    int i = blk & 255, h = (blk >> 8) & 3, b = blk >> 10;
    __shared__ float qs[DH];
    __shared__ float sp[NN];
    __shared__ float s8[8];
    if (j < DH) qs[j] = g_qkv[(size_t)(b * NN + i) * 768 + h * DH + j];
    __syncthreads();
    int adj = g_adj[(size_t)(b * NN + i) * NN + j];
    float sim = -FLT_MAX;
    if (adj) {
        const float* kr = g_qkv + (size_t)(b * NN + j) * 768 + 256 + h * DH;
        float d = 0.f;
#pragma unroll
        for (int t = 0; t < DH; t++) d += qs[t] * kr[t];
        sim = d * 0.125f + g_eb[((size_t)((b * NN + i) * NN) + j) * 4 + h];
    }
    float wm = wredmax(sim);
    if ((j & 31) == 0) s8[j >> 5] = wm;
    __syncthreads();
    float mx = s8[0];
#pragma unroll
    for (int k = 1; k < 8; k++) mx = fmaxf(mx, s8[k]);
    float ex = adj ? expf(sim - mx) : 0.f;
    __syncthreads();
    float wsum = wredsum(ex);
    if ((j & 31) == 0) s8[j >> 5] = wsum;
    __syncthreads();
    float tot = 0.f;
#pragma unroll
    for (int k = 0; k < 8; k++) tot += s8[k];
    float p = ex / tot;
    sp[j] = p;
    g_attn[((size_t)(b * HH + h) * NN + i) * NN + j] = p;
    __syncthreads();
    int d = j & 63, c0 = (j >> 6) * 64;
    float acc = 0.f;
    for (int jj = c0; jj < c0 + 64; jj++) {
        float pv = sp[jj];
        if (pv != 0.f)
            acc += pv * g_qkv[(size_t)(b * NN + jj) * 768 + 512 + h * DH + d];
    }
    __syncthreads();
    sp[j] = acc;
    __syncthreads();
    if (j < 64)
        g_tmp[(size_t)(b * NN + i) * INNER + h * DH + j] =
            sp[j] + sp[64 + j] + sp[128 + j] + sp[192 + j];
}

// ---------------- A_g with ballot-compacted neighbor list ----------------
__global__ void __launch_bounds__(256) k_Ag(const float* __restrict__ coords,
                     const float* __restrict__ w1, const float* __restrict__ b1) {
    int b = blockIdx.x >> 8, i = blockIdx.x & 255, m = threadIdx.x;
    int w = m >> 5, lane = m & 31;
    __shared__ float sa[HH][NN];
    __shared__ float scx[NN], scy[NN];
    __shared__ int slist[NN];
    __shared__ int wcnt[8], woff[8];
    __shared__ int scnt;
#pragma unroll
    for (int h = 0; h < HH; h++)
        sa[h][m] = g_attn[((size_t)(b * HH + h) * NN + i) * NN + m];
    int a = g_adj[(size_t)(b * NN + i) * NN + m];
    scx[m] = coords[(b * NN + m) * 2 + 0];
    scy[m] = coords[(b * NN + m) * 2 + 1];
    unsigned bal = __ballot_sync(0xffffffffu, a != 0);
    if (lane == 0) wcnt[w] = __popc(bal);
    __syncthreads();
    if (m == 0) {
        int s = 0;
#pragma unroll
        for (int k = 0; k < 8; k++) { woff[k] = s; s += wcnt[k]; }
        scnt = s;
    }
    __syncthreads();
    if (a) slist[woff[w] + __popc(bal & ((1u << lane) - 1u))] = m;
    __syncthreads();

    float w1r[10];
#pragma unroll
    for (int f = 0; f < 10; f++) w1r[f] = w1[f * INNER + m];
    float b1m = b1[m];
    float invls = 1.f / fmaxf(g_ls[b], 1e-6f);
    float cix = scx[i], ciy = scy[i];
    int hi = hop_of(i);
    float qic = (i == 0) ? 1.f : 0.f;
    float acc0 = 0, acc1 = 0, acc2 = 0, acc3 = 0;
    int nb = scnt;
    for (int t = 0; t < nb; t++) {
        int j = slist[t];
        float dx = scx[j] - cix, dy = scy[j] - ciy;
        float dist = sqrtf(dx * dx + dy * dy + 1e-8f);
        float kic = (j == 0) ? 1.f : 0.f;
        float ey = (i == j) ? 1.f : 0.f;
        float isnn = ((i != 0) && (j != 0) && (i != j)) ? 1.f : 0.f;
        int hj = hop_of(j);
        float hv = b1m + dx * w1r[0] + dy * w1r[1] + dist * w1r[2]
                 + (dist * invls) * w1r[3] + qic * w1r[4] + kic * w1r[5]
                 + ey * w1r[6] + isnn * w1r[7]
                 + ((hi == hj) ? 1.f : 0.f) * w1r[8]
                 + fabsf((float)(hj - hi)) * w1r[9];
        hv = gelu_f(hv);
        acc0 += sa[0][j] * hv;
        acc1 += sa[1][j] * hv;
        acc2 += sa[2][j] * hv;
        acc3 += sa[3][j] * hv;
    }
    size_t base = (size_t)(b * NN + i) * INNER + m;
    g_Ag[0 * (size_t)(BB * NN * INNER) + base] = acc0;
    g_Ag[1 * (size_t)(BB * NN * INNER) + base] = acc1;
    g_Ag[2 * (size_t)(BB * NN * INNER) + base] = acc2;
    g_Ag[3 * (size_t)(BB * NN * INNER) + base] = acc3;
}

// ---------------- host launch ----------------
extern "C" void kernel_launch(void* const* d_in, const int* in_sizes, int n_in,
                              void* d_out, int out_size) {
    const float* x      = (const float*)d_in[0];
    const float* coords = (const float*)d_in[1];
    const float* Wq     = (const float*)d_in[2];
    const float* Wk     = (const float*)d_in[3];
    const float* Wv     = (const float*)d_in[4];
    const float* ebw1   = (const float*)d_in[5];
    const float* ebb1   = (const float*)d_in[6];
    const float* ebw2   = (const float*)d_in[7];
    const float* ebb2   = (const float*)d_in[8];
    const float* evw1   = (const float*)d_in[9];
    const float* evb1   = (const float*)d_in[10];
    const float* evw2   = (const float*)d_in[11];
    const float* evb2   = (const float*)d_in[12];
    const float* Wo     = (const float*)d_in[13];
    const float* bo     = (const float*)d_in[14];
    const float* ln1w   = (const float*)d_in[15];
    const float* ln1b   = (const float*)d_in[16];
    const float* ln2w   = (const float*)d_in[17];
    const float* ln2b   = (const float*)d_in[18];
    const float* ffw1   = (const float*)d_in[19];
    const float* ffb1   = (const float*)d_in[20];
    const float* ffw2   = (const float*)d_in[21];
    const float* ffb2   = (const float*)d_in[22];

    static float *p_x = nullptr, *p_xn, *p_qkv, *p_wqkv, *p_tmp, *p_hg, *p_Ag;
    if (!p_x) {
        cudaGetSymbolAddress((void**)&p_x,    g_x);
        cudaGetSymbolAddress((void**)&p_xn,   g_xn);
        cudaGetSymbolAddress((void**)&p_qkv,  g_qkv);
        cudaGetSymbolAddress((void**)&p_wqkv, g_wqkv);
        cudaGetSymbolAddress((void**)&p_tmp,  g_tmp);
        cudaGetSymbolAddress((void**)&p_hg,   g_hg);
        cudaGetSymbolAddress((void**)&p_Ag,   g_Ag);
    }

    const int ROWS = BB * NN;   // 1024

    k_copy_in<<<ROWS, 64>>>(x);
    k_pack<<<(LL * DD * 768) / 256, 256>>>(Wq, Wk, Wv);
    k_valid<<<ROWS, 256>>>(x);
    k_ls<<<BB, NN>>>(coords);
    k_adj<<<BB, NN>>>(coords);

    for (int l = 0; l < LL; l++) {
        const float* ebw1_l = ebw1 + (size_t)l * 11 * INNER;
        const float* ebb1_l = ebb1 + (size_t)l * INNER;
        const float* ebw2_l = ebw2 + (size_t)l * INNER * HH;
        const float* ebb2_l = ebb2 + (size_t)l * HH;
        const float* evw1_l = evw1 + (size_t)l * 11 * INNER;
        const float* evb1_l = evb1 + (size_t)l * INNER;
        const float* evw2_l = evw2 + (size_t)l * INNER * INNER;
        const float* evb2_l = evb2 + (size_t)l * INNER;
        const float* Wo_l   = Wo   + (size_t)l * INNER * DD;
        const float* bo_l   = bo   + (size_t)l * DD;
        const float* ffw1_l = ffw1 + (size_t)l * DD * FFH;
        const float* ffb1_l = ffb1 + (size_t)l * FFH;
        const float* ffw2_l = ffw2 + (size_t)l * FFHALF * DD;
        const float* ffb2_l = ffb2 + (size_t)l * DD;

        k_layernorm<<<ROWS, 256>>>(p_x, ln1w + l * DD, ln1b + l * DD, p_xn);
        k_gemm2<false, false, false><<<dim3(768 / 64, ROWS / 64, 1), 256>>>(
            p_xn, p_wqkv + (size_t)l * DD * 768, nullptr, nullptr, p_qkv,
            DD, DD, 768, 768, 0, 0, 0, 0);
        k_eb<<<148, 256>>>(coords, ebw1_l, ebb1_l, ebw2_l, ebb2_l);
        k_attn<<<BB * HH * NN, 256>>>();
        k_Ag<<<BB * NN, 256>>>(coords, evw1_l, evb1_l);
        k_gemm2<false, true, true><<<dim3(1, ROWS / 64, HH), 256>>>(
            p_Ag, evw2_l, evb2_l, p_tmp, p_tmp,
            INNER, INNER, INNER, INNER,
            (long)BB * NN * INNER, 64, 64, 64);
        k_gemm2<false, true, true><<<dim3(DD / 64, ROWS / 64, 1), 256>>>(
            p_tmp, Wo_l, bo_l, p_x, p_x,
            INNER, INNER, DD, DD, 0, 0, 0, 0);
        k_layernorm<<<ROWS, 256>>>(p_x, ln2w + l * DD, ln2b + l * DD, p_xn);
        k_gemm2<false, true, false><<<dim3(FFH / 64, ROWS / 64, 1), 256>>>(
            p_xn, ffw1_l, ffb1_l, nullptr, p_hg,
            DD, DD, FFH, FFH, 0, 0, 0, 0);
        k_gemm2<true, true, true><<<dim3(DD / 64, ROWS / 64, 1), 256>>>(
            p_hg, ffw2_l, ffb2_l, p_x, p_x,
            FFHALF, FFH, DD, DD, 0, 0, 0, 0);
    }

    k_copy_out<<<ROWS, 64>>>((float*)d_out);
}